// round 3
// baseline (speedup 1.0000x reference)
#include <cuda_runtime.h>
#include <math.h>

// Problem constants
#define BB 8
#define DD 4096
#define NPROJ 12288      // 3*D
#define SS 16
#define FFD 16384
#define FIR_OFF 32768            // d_out offset of new_fir  (B*D elems of x first)
#define IIR_OFF 229376           // 32768 + 196608

typedef unsigned long long ull;

// ---------------- scratch (__device__ globals; no allocation allowed) -------
__device__ float g_xn1 [BB*DD];
__device__ float g_y   [BB*DD];
__device__ float g_xnew[BB*DD];
__device__ float g_xn2 [BB*DD];
__device__ float g_g   [BB*FFD];
__device__ float g_ssq [BB];
__device__ float g_pA  [2097152];   // split-K partials
__device__ float g_pB  [2097152];

__device__ __forceinline__ void fma2(ull& a, ull w, ull x) {
    asm("fma.rn.f32x2 %0, %1, %2, %0;" : "+l"(a) : "l"(w), "l"(x));
}

// ---------------- rmsnorm of input x ----------------------------------------
__global__ void rmsnorm1_kernel(const float* __restrict__ x,
                                const float* __restrict__ w,
                                float* __restrict__ out) {
    int b = blockIdx.x;          // 8 blocks
    int tid = threadIdx.x;       // 512 threads
    float v[8];
    float ss = 0.f;
#pragma unroll
    for (int e = 0; e < 8; e++) {
        float t = x[b*DD + e*512 + tid];
        v[e] = t; ss += t*t;
    }
    __shared__ float red[16];
    int lane = tid & 31, wid = tid >> 5;
#pragma unroll
    for (int o = 16; o; o >>= 1) ss += __shfl_xor_sync(0xffffffffu, ss, o);
    if (lane == 0) red[wid] = ss;
    __syncthreads();
    if (tid == 0) { float t = 0.f; for (int i = 0; i < 16; i++) t += red[i]; red[0] = t; }
    __syncthreads();
    float scale = rsqrtf(red[0] * (1.f/DD) + 1e-6f);
#pragma unroll
    for (int e = 0; e < 8; e++)
        out[b*DD + e*512 + tid] = v[e] * scale * w[e*512 + tid];
}

// ---------------- split-K GEMV: software-pipelined loads + f32x2 FMA --------
// P[chunk][b][n] = sum_{k in chunk} X[b][k] * W[k][n]
// KCH must be a multiple of 16 and >= 32.
template<int KCH>
__global__ __launch_bounds__(256, 2)
void gemv_partial(const float* __restrict__ W,
                  const float* __restrict__ X,
                  float* __restrict__ P, int K, int N) {
    __shared__ float2 xs2[8*KCH];        // activation duplicated (x,x) for LDS.64
    int tid = threadIdx.x;               // 256 threads
    int k0  = blockIdx.y * KCH;
#pragma unroll
    for (int i = tid; i < 8*KCH; i += 256) {
        int b = i / KCH, k = i % KCH;
        float v = X[b*K + k0 + k];
        xs2[i] = make_float2(v, v);
    }
    __syncthreads();

    int Nv = N >> 2;                     // float4 columns
    int col4 = blockIdx.x*256 + tid;
    const ulonglong2* Wv = reinterpret_cast<const ulonglong2*>(W)
                         + (size_t)k0*Nv + col4;
    ull acc[8][2];
#pragma unroll
    for (int b = 0; b < 8; b++) { acc[b][0] = 0ull; acc[b][1] = 0ull; }

    ulonglong2 buf0[8], buf1[8];

    // prologue: load rows 0..7
#pragma unroll
    for (int i = 0; i < 8; i++) buf0[i] = Wv[(size_t)i*Nv];

    // pipelined main loop: prefetch next 8 while computing current 8
#pragma unroll 1
    for (int k = 0; k < KCH-16; k += 16) {
#pragma unroll
        for (int i = 0; i < 8; i++) {
            buf1[i] = Wv[(size_t)(k+8+i)*Nv];
#pragma unroll
            for (int b = 0; b < 8; b++) {
                ull xx = *reinterpret_cast<const ull*>(&xs2[b*KCH + k + i]);
                fma2(acc[b][0], buf0[i].x, xx);
                fma2(acc[b][1], buf0[i].y, xx);
            }
        }
#pragma unroll
        for (int i = 0; i < 8; i++) {
            buf0[i] = Wv[(size_t)(k+16+i)*Nv];
#pragma unroll
            for (int b = 0; b < 8; b++) {
                ull xx = *reinterpret_cast<const ull*>(&xs2[b*KCH + k+8 + i]);
                fma2(acc[b][0], buf1[i].x, xx);
                fma2(acc[b][1], buf1[i].y, xx);
            }
        }
    }
    // epilogue: k = KCH-16 — buf0 holds rows KCH-16..KCH-9
    {
        const int k = KCH-16;
#pragma unroll
        for (int i = 0; i < 8; i++) {
            buf1[i] = Wv[(size_t)(k+8+i)*Nv];
#pragma unroll
            for (int b = 0; b < 8; b++) {
                ull xx = *reinterpret_cast<const ull*>(&xs2[b*KCH + k + i]);
                fma2(acc[b][0], buf0[i].x, xx);
                fma2(acc[b][1], buf0[i].y, xx);
            }
        }
#pragma unroll
        for (int i = 0; i < 8; i++) {
#pragma unroll
            for (int b = 0; b < 8; b++) {
                ull xx = *reinterpret_cast<const ull*>(&xs2[b*KCH + k+8 + i]);
                fma2(acc[b][0], buf1[i].x, xx);
                fma2(acc[b][1], buf1[i].y, xx);
            }
        }
    }

    ulonglong2* Pv = reinterpret_cast<ulonglong2*>(P)
                   + (size_t)blockIdx.y*(N<<1) + col4;
#pragma unroll
    for (int b = 0; b < 8; b++)
        Pv[(size_t)b*Nv] = make_ulonglong2(acc[b][0], acc[b][1]);
}

// ---------------- FIR + gating split + IIR (reduces proj partials, 16 chunks)
__global__ void fir_iir_kernel(const float* __restrict__ P,
                               const float* __restrict__ fir_state,
                               const float* __restrict__ sfw,
                               const float* __restrict__ sfb,
                               const float* __restrict__ iir,
                               const float* __restrict__ lp,
                               const float* __restrict__ resid,
                               const float* __restrict__ Dres,
                               float* __restrict__ y,
                               float* __restrict__ dout) {
    int blk = blockIdx.x;                // 256 blocks = 8 batch * 32 heads
    int b = blk >> 5, h = blk & 31;
    int j = threadIdx.x;                 // 128 threads = DPH
    if (blk == 0 && j < BB) g_ssq[j] = 0.f;   // pre-zero for reduce_res

    float zp[3];
#pragma unroll
    for (int e = 0; e < 3; e++) {
        int i  = h*384 + e*128 + j;
        int gi = b*NPROJ + i;
        float u = 0.f;
#pragma unroll
        for (int c = 0; c < 16; c++) u += P[c*(8*NPROJ) + gi];
        float f0 = fir_state[gi*2 + 0];
        float f1 = fir_state[gi*2 + 1];
        float w0 = sfw[i*3 + 0], w1 = sfw[i*3 + 1], w2 = sfw[i*3 + 2];
        zp[e] = w2*u + f0*w0 + f1*w1 + sfb[i];
        dout[FIR_OFF + gi*2 + 0] = f1;   // new_fir = [f1, u]
        dout[FIR_OFF + gi*2 + 1] = u;
    }
    int d = h*128 + j;
    float x2 = zp[0], x1 = zp[1], v = zp[2];
    float x1v = x1 * v;
    float res = 0.f;
    int base = (b*DD + d)*SS;
#pragma unroll
    for (int s = 0; s < SS; s++) {
        float pole = expf(lp[d*SS + s]);
        float ni = fmaf(pole, iir[base + s], x1v);
        dout[IIR_OFF + base + s] = ni;
        res = fmaf(resid[d*SS + s], ni, res);
    }
    y[b*DD + d] = x2 * (res + Dres[d]*x1v);
}

// ---------------- reduce out_w partials (64 chunks) + bias + residual + ssq --
__global__ void reduce_res_kernel(const float4* __restrict__ P4,
                                  const float4* __restrict__ x4,
                                  const float4* __restrict__ ob4,
                                  float4* __restrict__ xnew4) {
    int g4 = blockIdx.x*256 + threadIdx.x;    // 8192 float4 total, 32 blocks
    int b = g4 >> 10, n4 = g4 & 1023;
    float4 v = x4[g4], o = ob4[n4];
    v.x += o.x; v.y += o.y; v.z += o.z; v.w += o.w;
#pragma unroll
    for (int c = 0; c < 64; c++) {
        float4 p = P4[c*8192 + g4];
        v.x += p.x; v.y += p.y; v.z += p.z; v.w += p.w;
    }
    xnew4[g4] = v;
    float ss = v.x*v.x + v.y*v.y + v.z*v.z + v.w*v.w;
#pragma unroll
    for (int o2 = 16; o2; o2 >>= 1) ss += __shfl_xor_sync(0xffffffffu, ss, o2);
    __shared__ float red[8];
    int lane = threadIdx.x & 31, wid = threadIdx.x >> 5;
    if (lane == 0) red[wid] = ss;
    __syncthreads();
    if (threadIdx.x == 0) {
        float t = 0.f;
        for (int i = 0; i < 8; i++) t += red[i];
        atomicAdd(&g_ssq[b], t);
    }
}

// ---------------- post-norm scale -------------------------------------------
__global__ void scale_kernel(const float* __restrict__ xnew,
                             const float* __restrict__ w,
                             float* __restrict__ xn2) {
    int gid = blockIdx.x*256 + threadIdx.x;
    int b = gid >> 12, n = gid & (DD-1);
    xn2[gid] = xnew[gid] * rsqrtf(g_ssq[b]*(1.f/DD) + 1e-6f) * w[n];
}

// ---------------- SwiGLU: g = silu(sum pA) * (sum pB)  (16 chunks each) ------
__global__ void glu_kernel(const float4* __restrict__ PA4,
                           const float4* __restrict__ PB4,
                           float4* __restrict__ g4out) {
    int g4 = blockIdx.x*256 + threadIdx.x;    // 32768 float4, 128 blocks
    float4 a = make_float4(0,0,0,0), c3 = make_float4(0,0,0,0);
#pragma unroll
    for (int c = 0; c < 16; c++) {
        float4 pa = PA4[c*32768 + g4];
        float4 pb = PB4[c*32768 + g4];
        a.x += pa.x; a.y += pa.y; a.z += pa.z; a.w += pa.w;
        c3.x += pb.x; c3.y += pb.y; c3.z += pb.z; c3.w += pb.w;
    }
    float4 r;
    r.x = (a.x / (1.f + expf(-a.x))) * c3.x;
    r.y = (a.y / (1.f + expf(-a.y))) * c3.y;
    r.z = (a.z / (1.f + expf(-a.z))) * c3.z;
    r.w = (a.w / (1.f + expf(-a.w))) * c3.w;
    g4out[g4] = r;
}

// ---------------- final: x_out = xnew + reduce64(mlp_w2 partials) ------------
__global__ void final_kernel(const float4* __restrict__ P4,
                             const float4* __restrict__ xnew4,
                             float4* __restrict__ dout4) {
    int g4 = blockIdx.x*256 + threadIdx.x;    // 8192 float4, 32 blocks
    float4 v = xnew4[g4];
#pragma unroll
    for (int c = 0; c < 64; c++) {
        float4 p = P4[c*8192 + g4];
        v.x += p.x; v.y += p.y; v.z += p.z; v.w += p.w;
    }
    dout4[g4] = v;
}

// ---------------- host launcher ----------------------------------------------
extern "C" void kernel_launch(void* const* d_in, const int* in_sizes, int n_in,
                              void* d_out, int out_size) {
    (void)in_sizes; (void)n_in; (void)out_size;
    const float* x          = (const float*)d_in[0];
    const float* fir_state  = (const float*)d_in[1];
    const float* iir_state  = (const float*)d_in[2];
    const float* pre_w      = (const float*)d_in[3];
    const float* proj_w     = (const float*)d_in[4];
    const float* sfw        = (const float*)d_in[5];
    const float* sfb        = (const float*)d_in[6];
    const float* Dres       = (const float*)d_in[7];
    const float* resid      = (const float*)d_in[8];
    const float* lp         = (const float*)d_in[9];
    const float* out_w      = (const float*)d_in[10];
    const float* out_b      = (const float*)d_in[11];
    const float* post_w     = (const float*)d_in[12];
    const float* w1         = (const float*)d_in[13];
    const float* w3         = (const float*)d_in[14];
    const float* w2         = (const float*)d_in[15];
    float* out = (float*)d_out;

    float *xn1, *y, *xnew, *xn2, *g, *pA, *pB;
    cudaGetSymbolAddress((void**)&xn1,  g_xn1);
    cudaGetSymbolAddress((void**)&y,    g_y);
    cudaGetSymbolAddress((void**)&xnew, g_xnew);
    cudaGetSymbolAddress((void**)&xn2,  g_xn2);
    cudaGetSymbolAddress((void**)&g,    g_g);
    cudaGetSymbolAddress((void**)&pA,   g_pA);
    cudaGetSymbolAddress((void**)&pB,   g_pB);

    // 1. pre-norm
    rmsnorm1_kernel<<<BB, 512>>>(x, pre_w, xn1);
    // 2. z = xn1 @ proj_w (4096x12288): 12 col-blocks x 16 chunks = 192 blocks
    gemv_partial<256><<<dim3(12,16), 256>>>(proj_w, xn1, pA, DD, NPROJ);
    // 3. FIR + split + IIR -> y, new_fir, new_iir (also zeroes g_ssq)
    fir_iir_kernel<<<256, 128>>>(pA, fir_state, sfw, sfb, iir_state, lp, resid, Dres, y, out);
    // 4. y @ out_w (4096x4096): 4 col-blocks x 64 chunks = 256 blocks
    gemv_partial<64><<<dim3(4,64), 256>>>(out_w, y, pA, DD, DD);
    // 5. xnew = reduce + out_b + x; accumulate sum of squares
    reduce_res_kernel<<<32, 256>>>((const float4*)pA, (const float4*)x,
                                   (const float4*)out_b, (float4*)xnew);
    // 6. xn2 = rmsnorm(xnew) * post_w
    scale_kernel<<<128, 256>>>(xnew, post_w, xn2);
    // 7/8. MLP up (4096x16384): 16 col-blocks x 16 chunks = 256 blocks each
    gemv_partial<256><<<dim3(16,16), 256>>>(w1, xn2, pA, DD, FFD);
    gemv_partial<256><<<dim3(16,16), 256>>>(w3, xn2, pB, DD, FFD);
    // 9. SwiGLU gate
    glu_kernel<<<128, 256>>>((const float4*)pA, (const float4*)pB, (float4*)g);
    // 10. g @ mlp_w2 (16384x4096): 4 col-blocks x 64 chunks = 256 blocks
    gemv_partial<256><<<dim3(4,64), 256>>>(w2, g, pA, FFD, DD);
    // 11. x_out = xnew + reduce
    final_kernel<<<32, 256>>>((const float4*)pA, (const float4*)xnew, (float4*)out);
}

// round 4
// speedup vs baseline: 1.0327x; 1.0327x over previous
#include <cuda_runtime.h>
#include <math.h>

// Problem constants
#define BB 8
#define DD 4096
#define NPROJ 12288      // 3*D
#define SS 16
#define FFD 16384
#define FIR_OFF 32768            // d_out offset of new_fir  (B*D elems of x first)
#define IIR_OFF 229376           // 32768 + 196608

typedef unsigned long long ull;

// ---------------- scratch (__device__ globals; no allocation allowed) -------
__device__ float g_xn1 [BB*DD];
__device__ float g_y   [BB*DD];
__device__ float g_xnew[BB*DD];
__device__ float g_xn2 [BB*DD];
__device__ float g_g   [BB*FFD];
__device__ float g_ssq [BB];
__device__ float g_pA  [2097152];   // split-K partials
__device__ float g_pB  [2097152];

__device__ __forceinline__ void fma2(ull& a, ull w, ull x) {
    asm("fma.rn.f32x2 %0, %1, %2, %0;" : "+l"(a) : "l"(w), "l"(x));
}
__device__ __forceinline__ void cp_async16(void* sdst, const void* gsrc) {
    unsigned s = (unsigned)__cvta_generic_to_shared(sdst);
    asm volatile("cp.async.cg.shared.global [%0], [%1], 16;" :: "r"(s), "l"(gsrc));
}
__device__ __forceinline__ void cp_commit() {
    asm volatile("cp.async.commit_group;");
}
template<int N> __device__ __forceinline__ void cp_wait() {
    asm volatile("cp.async.wait_group %0;" :: "n"(N));
}

// ---------------- rmsnorm of input x ----------------------------------------
__global__ void rmsnorm1_kernel(const float* __restrict__ x,
                                const float* __restrict__ w,
                                float* __restrict__ out) {
    int b = blockIdx.x;          // 8 blocks
    int tid = threadIdx.x;       // 512 threads
    float v[8];
    float ss = 0.f;
#pragma unroll
    for (int e = 0; e < 8; e++) {
        float t = x[b*DD + e*512 + tid];
        v[e] = t; ss += t*t;
    }
    __shared__ float red[16];
    int lane = tid & 31, wid = tid >> 5;
#pragma unroll
    for (int o = 16; o; o >>= 1) ss += __shfl_xor_sync(0xffffffffu, ss, o);
    if (lane == 0) red[wid] = ss;
    __syncthreads();
    if (tid == 0) { float t = 0.f; for (int i = 0; i < 16; i++) t += red[i]; red[0] = t; }
    __syncthreads();
    float scale = rsqrtf(red[0] * (1.f/DD) + 1e-6f);
#pragma unroll
    for (int e = 0; e < 8; e++)
        out[b*DD + e*512 + tid] = v[e] * scale * w[e*512 + tid];
}

// ---------------- split-K GEMV: cp.async double-buffered smem staging -------
// P[chunk][b][n] = sum_{k in chunk} X[b][k] * W[k][n]
// KCH multiple of 16. Dynamic smem: 8*KCH*8 (xs2) + 2*8*256*16 (weight stages)
template<int KCH>
__global__ __launch_bounds__(256, 2)
void gemv_partial(const float* __restrict__ W,
                  const float* __restrict__ X,
                  float* __restrict__ P, int K, int N) {
    extern __shared__ char smem[];
    float2*     xs2  = reinterpret_cast<float2*>(smem);                 // 8*KCH
    ulonglong2* wbuf = reinterpret_cast<ulonglong2*>(smem + 8*KCH*8);   // 2*8*256

    int tid = threadIdx.x;               // 256 threads
    int k0  = blockIdx.y * KCH;
#pragma unroll
    for (int i = tid; i < 8*KCH; i += 256) {
        int b = i / KCH, k = i % KCH;
        float v = X[b*K + k0 + k];
        xs2[i] = make_float2(v, v);
    }
    __syncthreads();

    int Nv = N >> 2;                     // float4 columns
    int col4 = blockIdx.x*256 + tid;
    const float4* Wv = reinterpret_cast<const float4*>(W) + (size_t)k0*Nv + col4;

    // prologue: stage 0 and stage 1 (each 8 rows, 16 B per thread per row)
#pragma unroll
    for (int i = 0; i < 8; i++)
        cp_async16(&wbuf[(0*8 + i)*256 + tid], Wv + (size_t)i*Nv);
    cp_commit();
#pragma unroll
    for (int i = 0; i < 8; i++)
        cp_async16(&wbuf[(1*8 + i)*256 + tid], Wv + (size_t)(8+i)*Nv);
    cp_commit();

    ull acc[8][2];
#pragma unroll
    for (int b = 0; b < 8; b++) { acc[b][0] = 0ull; acc[b][1] = 0ull; }

    const int nstages = KCH / 8;
#pragma unroll 1
    for (int s = 0; s < nstages; s++) {
        if (s + 1 < nstages) cp_wait<1>(); else cp_wait<0>();
        int sb = s & 1;
        const ulonglong2* ws = wbuf + sb*2048 + tid;
        int kb = s*8;
#pragma unroll
        for (int i = 0; i < 8; i++) {
            ulonglong2 wv = ws[i*256];
#pragma unroll
            for (int b = 0; b < 8; b++) {
                ull xx = *reinterpret_cast<const ull*>(&xs2[b*KCH + kb + i]);
                fma2(acc[b][0], wv.x, xx);
                fma2(acc[b][1], wv.y, xx);
            }
        }
        // prefetch stage s+2 into the buffer just consumed
        if (s + 2 < nstages) {
            const float4* src = Wv + (size_t)(s+2)*8*Nv;
#pragma unroll
            for (int i = 0; i < 8; i++)
                cp_async16(&wbuf[(sb*8 + i)*256 + tid], src + (size_t)i*Nv);
            cp_commit();
        }
    }

    ulonglong2* Pv = reinterpret_cast<ulonglong2*>(P)
                   + (size_t)blockIdx.y*(N<<1) + col4;
#pragma unroll
    for (int b = 0; b < 8; b++)
        Pv[(size_t)b*Nv] = make_ulonglong2(acc[b][0], acc[b][1]);
}

// ---------------- FIR + gating split + IIR (reduces proj partials, 16 chunks)
__global__ void fir_iir_kernel(const float* __restrict__ P,
                               const float* __restrict__ fir_state,
                               const float* __restrict__ sfw,
                               const float* __restrict__ sfb,
                               const float* __restrict__ iir,
                               const float* __restrict__ lp,
                               const float* __restrict__ resid,
                               const float* __restrict__ Dres,
                               float* __restrict__ y,
                               float* __restrict__ dout) {
    int blk = blockIdx.x;                // 256 blocks = 8 batch * 32 heads
    int b = blk >> 5, h = blk & 31;
    int j = threadIdx.x;                 // 128 threads = DPH
    if (blk == 0 && j < BB) g_ssq[j] = 0.f;   // pre-zero for reduce_res

    float zp[3];
#pragma unroll
    for (int e = 0; e < 3; e++) {
        int i  = h*384 + e*128 + j;
        int gi = b*NPROJ + i;
        float u = 0.f;
#pragma unroll
        for (int c = 0; c < 16; c++) u += P[c*(8*NPROJ) + gi];
        float f0 = fir_state[gi*2 + 0];
        float f1 = fir_state[gi*2 + 1];
        float w0 = sfw[i*3 + 0], w1 = sfw[i*3 + 1], w2 = sfw[i*3 + 2];
        zp[e] = w2*u + f0*w0 + f1*w1 + sfb[i];
        dout[FIR_OFF + gi*2 + 0] = f1;   // new_fir = [f1, u]
        dout[FIR_OFF + gi*2 + 1] = u;
    }
    int d = h*128 + j;
    float x2 = zp[0], x1 = zp[1], v = zp[2];
    float x1v = x1 * v;
    float res = 0.f;
    int base = (b*DD + d)*SS;
#pragma unroll
    for (int s = 0; s < SS; s++) {
        float pole = expf(lp[d*SS + s]);
        float ni = fmaf(pole, iir[base + s], x1v);
        dout[IIR_OFF + base + s] = ni;
        res = fmaf(resid[d*SS + s], ni, res);
    }
    y[b*DD + d] = x2 * (res + Dres[d]*x1v);
}

// ---------------- reduce out_w partials (64 chunks) + bias + residual + ssq --
__global__ void reduce_res_kernel(const float4* __restrict__ P4,
                                  const float4* __restrict__ x4,
                                  const float4* __restrict__ ob4,
                                  float4* __restrict__ xnew4) {
    int g4 = blockIdx.x*256 + threadIdx.x;    // 8192 float4 total, 32 blocks
    int b = g4 >> 10, n4 = g4 & 1023;
    float4 v = x4[g4], o = ob4[n4];
    v.x += o.x; v.y += o.y; v.z += o.z; v.w += o.w;
#pragma unroll
    for (int c = 0; c < 64; c++) {
        float4 p = P4[c*8192 + g4];
        v.x += p.x; v.y += p.y; v.z += p.z; v.w += p.w;
    }
    xnew4[g4] = v;
    float ss = v.x*v.x + v.y*v.y + v.z*v.z + v.w*v.w;
#pragma unroll
    for (int o2 = 16; o2; o2 >>= 1) ss += __shfl_xor_sync(0xffffffffu, ss, o2);
    __shared__ float red[8];
    int lane = threadIdx.x & 31, wid = threadIdx.x >> 5;
    if (lane == 0) red[wid] = ss;
    __syncthreads();
    if (threadIdx.x == 0) {
        float t = 0.f;
        for (int i = 0; i < 8; i++) t += red[i];
        atomicAdd(&g_ssq[b], t);
    }
}

// ---------------- post-norm scale -------------------------------------------
__global__ void scale_kernel(const float* __restrict__ xnew,
                             const float* __restrict__ w,
                             float* __restrict__ xn2) {
    int gid = blockIdx.x*256 + threadIdx.x;
    int b = gid >> 12, n = gid & (DD-1);
    xn2[gid] = xnew[gid] * rsqrtf(g_ssq[b]*(1.f/DD) + 1e-6f) * w[n];
}

// ---------------- SwiGLU: g = silu(sum pA) * (sum pB)  (16 chunks each) ------
__global__ void glu_kernel(const float4* __restrict__ PA4,
                           const float4* __restrict__ PB4,
                           float4* __restrict__ g4out) {
    int g4 = blockIdx.x*256 + threadIdx.x;    // 32768 float4, 128 blocks
    float4 a = make_float4(0,0,0,0), c3 = make_float4(0,0,0,0);
#pragma unroll
    for (int c = 0; c < 16; c++) {
        float4 pa = PA4[c*32768 + g4];
        float4 pb = PB4[c*32768 + g4];
        a.x += pa.x; a.y += pa.y; a.z += pa.z; a.w += pa.w;
        c3.x += pb.x; c3.y += pb.y; c3.z += pb.z; c3.w += pb.w;
    }
    float4 r;
    r.x = (a.x / (1.f + expf(-a.x))) * c3.x;
    r.y = (a.y / (1.f + expf(-a.y))) * c3.y;
    r.z = (a.z / (1.f + expf(-a.z))) * c3.z;
    r.w = (a.w / (1.f + expf(-a.w))) * c3.w;
    g4out[g4] = r;
}

// ---------------- final: x_out = xnew + reduce64(mlp_w2 partials) ------------
__global__ void final_kernel(const float4* __restrict__ P4,
                             const float4* __restrict__ xnew4,
                             float4* __restrict__ dout4) {
    int g4 = blockIdx.x*256 + threadIdx.x;    // 8192 float4, 32 blocks
    float4 v = xnew4[g4];
#pragma unroll
    for (int c = 0; c < 64; c++) {
        float4 p = P4[c*8192 + g4];
        v.x += p.x; v.y += p.y; v.z += p.z; v.w += p.w;
    }
    dout4[g4] = v;
}

// ---------------- host launcher ----------------------------------------------
extern "C" void kernel_launch(void* const* d_in, const int* in_sizes, int n_in,
                              void* d_out, int out_size) {
    (void)in_sizes; (void)n_in; (void)out_size;
    const float* x          = (const float*)d_in[0];
    const float* fir_state  = (const float*)d_in[1];
    const float* iir_state  = (const float*)d_in[2];
    const float* pre_w      = (const float*)d_in[3];
    const float* proj_w     = (const float*)d_in[4];
    const float* sfw        = (const float*)d_in[5];
    const float* sfb        = (const float*)d_in[6];
    const float* Dres       = (const float*)d_in[7];
    const float* resid      = (const float*)d_in[8];
    const float* lp         = (const float*)d_in[9];
    const float* out_w      = (const float*)d_in[10];
    const float* out_b      = (const float*)d_in[11];
    const float* post_w     = (const float*)d_in[12];
    const float* w1         = (const float*)d_in[13];
    const float* w3         = (const float*)d_in[14];
    const float* w2         = (const float*)d_in[15];
    float* out = (float*)d_out;

    float *xn1, *y, *xnew, *xn2, *g, *pA, *pB;
    cudaGetSymbolAddress((void**)&xn1,  g_xn1);
    cudaGetSymbolAddress((void**)&y,    g_y);
    cudaGetSymbolAddress((void**)&xnew, g_xnew);
    cudaGetSymbolAddress((void**)&xn2,  g_xn2);
    cudaGetSymbolAddress((void**)&g,    g_g);
    cudaGetSymbolAddress((void**)&pA,   g_pA);
    cudaGetSymbolAddress((void**)&pB,   g_pB);

    // dynamic smem sizes: xs2 (8*KCH*8 bytes) + weight stages (65536 bytes)
    const int smem256 = 8*256*8 + 65536;   // 81920
    const int smem64  = 8*64*8  + 65536;   // 69632
    cudaFuncSetAttribute(gemv_partial<256>,
                         cudaFuncAttributeMaxDynamicSharedMemorySize, smem256);
    cudaFuncSetAttribute(gemv_partial<64>,
                         cudaFuncAttributeMaxDynamicSharedMemorySize, smem64);

    // 1. pre-norm
    rmsnorm1_kernel<<<BB, 512>>>(x, pre_w, xn1);
    // 2. z = xn1 @ proj_w (4096x12288): 12 col-blocks x 16 chunks = 192 blocks
    gemv_partial<256><<<dim3(12,16), 256, smem256>>>(proj_w, xn1, pA, DD, NPROJ);
    // 3. FIR + split + IIR -> y, new_fir, new_iir (also zeroes g_ssq)
    fir_iir_kernel<<<256, 128>>>(pA, fir_state, sfw, sfb, iir_state, lp, resid, Dres, y, out);
    // 4. y @ out_w (4096x4096): 4 col-blocks x 64 chunks = 256 blocks
    gemv_partial<64><<<dim3(4,64), 256, smem64>>>(out_w, y, pA, DD, DD);
    // 5. xnew = reduce + out_b + x; accumulate sum of squares
    reduce_res_kernel<<<32, 256>>>((const float4*)pA, (const float4*)x,
                                   (const float4*)out_b, (float4*)xnew);
    // 6. xn2 = rmsnorm(xnew) * post_w
    scale_kernel<<<128, 256>>>(xnew, post_w, xn2);
    // 7/8. MLP up (4096x16384): 16 col-blocks x 16 chunks = 256 blocks each
    gemv_partial<256><<<dim3(16,16), 256, smem256>>>(w1, xn2, pA, DD, FFD);
    gemv_partial<256><<<dim3(16,16), 256, smem256>>>(w3, xn2, pB, DD, FFD);
    // 9. SwiGLU gate
    glu_kernel<<<128, 256>>>((const float4*)pA, (const float4*)pB, (float4*)g);
    // 10. g @ mlp_w2 (16384x4096): 4 col-blocks x 64 chunks = 256 blocks
    gemv_partial<256><<<dim3(4,64), 256, smem256>>>(w2, g, pA, FFD, DD);
    // 11. x_out = xnew + reduce
    final_kernel<<<32, 256>>>((const float4*)pA, (const float4*)xnew, (float4*)out);
}